// round 7
// baseline (speedup 1.0000x reference)
#include <cuda_runtime.h>
#include <cuda_bf16.h>
#include <cstdint>

constexpr int B = 2, C = 2, D = 160, H = 192, W = 224;
constexpr int HW  = H * W;          // 43008
constexpr int DHW = D * H * W;      // 6,881,280

__global__ __launch_bounds__(256, 8)
void affine_grid_sample_kernel(const float* __restrict__ src,
                               const float* __restrict__ mat,
                               float* __restrict__ out)
{
    const int w  = blockIdx.x * 32 + threadIdx.x;   // 0..W-1 (warp = 32 consecutive w)
    const int h  = blockIdx.y * 8  + threadIdx.y;   // 0..H-1
    const int zz = blockIdx.z;                      // 0..B*D-1
    const int b  = (zz >= D) ? 1 : 0;
    const int d  = zz - (b ? D : 0);

    const float4* m4 = (const float4*)(mat + b * 12);
    const float4 r0 = __ldg(m4 + 0);
    const float4 r1 = __ldg(m4 + 1);
    const float4 r2 = __ldg(m4 + 2);

    const float yn = fmaf((float)h, 2.0f / (H - 1), -1.0f);
    const float zn = fmaf((float)d, 2.0f / (D - 1), -1.0f);
    const float wf = (float)w;

    const float hw_ = 0.5f * (W - 1);
    const float hh_ = 0.5f * (H - 1);
    const float hd_ = 0.5f * (D - 1);

    // ix = r0.x*w + hw_*(r0.y*yn + r0.z*zn + r0.w/D + 1 - r0.x), etc.
    const float tx = fmaf(r0.y, yn, fmaf(r0.z, zn, fmaf(r0.w, 1.0f / D, 1.0f - r0.x)));
    const float ty = fmaf(r1.y, yn, fmaf(r1.z, zn, fmaf(r1.w, 1.0f / H, 1.0f - r1.x)));
    const float tz = fmaf(r2.y, yn, fmaf(r2.z, zn, fmaf(r2.w, 1.0f / W, 1.0f - r2.x)));

    const float ix = fmaf(r0.x,               wf, tx * hw_);
    const float iy = fmaf(r1.x * (hh_ / hw_), wf, ty * hh_);
    const float iz = fmaf(r2.x * (hd_ / hw_), wf, tz * hd_);

    const float fx0 = floorf(ix), fy0 = floorf(iy), fz0 = floorf(iz);
    const float fx = ix - fx0, fy = iy - fy0, fz = iz - fz0;
    const int x0 = (int)fx0, y0 = (int)fy0, z0 = (int)fz0;

    // trilinear weights
    const float wx1 = fx, wx0 = 1.0f - fx;
    const float wy1 = fy, wy0 = 1.0f - fy;
    const float wz1 = fz, wz0 = 1.0f - fz;
    const float w00 = wz0 * wy0, w01 = wz0 * wy1;
    const float w10 = wz1 * wy0, w11 = wz1 * wy1;
    const float w000 = w00 * wx0, w001 = w00 * wx1;
    const float w010 = w01 * wx0, w011 = w01 * wx1;
    const float w100 = w10 * wx0, w101 = w10 * wx1;
    const float w110 = w11 * wx0, w111 = w11 * wx1;

    const float* sb = src + (size_t)b * (size_t)(C * DHW);
    const float* p  = sb + ((size_t)((z0 * H + y0) * W + x0));
    const float* q  = p + DHW;

    float acc0, acc1;

    const bool interior = ((unsigned)x0 < (unsigned)(W - 1)) &
                          ((unsigned)y0 < (unsigned)(H - 1)) &
                          ((unsigned)z0 < (unsigned)(D - 1));

    if (interior) {
        // fast path: no predicates, no zero-init
        float a000 = __ldg(p);
        float a001 = __ldg(p + 1);
        float a010 = __ldg(p + W);
        float a011 = __ldg(p + W + 1);
        float a100 = __ldg(p + HW);
        float a101 = __ldg(p + HW + 1);
        float a110 = __ldg(p + HW + W);
        float a111 = __ldg(p + HW + W + 1);
        float c000 = __ldg(q);
        float c001 = __ldg(q + 1);
        float c010 = __ldg(q + W);
        float c011 = __ldg(q + W + 1);
        float c100 = __ldg(q + HW);
        float c101 = __ldg(q + HW + 1);
        float c110 = __ldg(q + HW + W);
        float c111 = __ldg(q + HW + W + 1);

        acc0 = w000 * a000;
        acc0 = fmaf(w001, a001, acc0);
        acc0 = fmaf(w010, a010, acc0);
        acc0 = fmaf(w011, a011, acc0);
        acc0 = fmaf(w100, a100, acc0);
        acc0 = fmaf(w101, a101, acc0);
        acc0 = fmaf(w110, a110, acc0);
        acc0 = fmaf(w111, a111, acc0);

        acc1 = w000 * c000;
        acc1 = fmaf(w001, c001, acc1);
        acc1 = fmaf(w010, c010, acc1);
        acc1 = fmaf(w011, c011, acc1);
        acc1 = fmaf(w100, c100, acc1);
        acc1 = fmaf(w101, c101, acc1);
        acc1 = fmaf(w110, c110, acc1);
        acc1 = fmaf(w111, c111, acc1);
    } else {
        // border path: per-corner validity, zero padding
        const bool vx0 = (unsigned)x0       < (unsigned)W;
        const bool vx1 = (unsigned)(x0 + 1) < (unsigned)W;
        const bool vy0 = (unsigned)y0       < (unsigned)H;
        const bool vy1 = (unsigned)(y0 + 1) < (unsigned)H;
        const bool vz0 = (unsigned)z0       < (unsigned)D;
        const bool vz1 = (unsigned)(z0 + 1) < (unsigned)D;

        const bool p000 = vz0 & vy0 & vx0, p001 = vz0 & vy0 & vx1;
        const bool p010 = vz0 & vy1 & vx0, p011 = vz0 & vy1 & vx1;
        const bool p100 = vz1 & vy0 & vx0, p101 = vz1 & vy0 & vx1;
        const bool p110 = vz1 & vy1 & vx0, p111 = vz1 & vy1 & vx1;

        float a000 = p000 ? __ldg(p)              : 0.0f;
        float a001 = p001 ? __ldg(p + 1)          : 0.0f;
        float a010 = p010 ? __ldg(p + W)          : 0.0f;
        float a011 = p011 ? __ldg(p + W + 1)      : 0.0f;
        float a100 = p100 ? __ldg(p + HW)         : 0.0f;
        float a101 = p101 ? __ldg(p + HW + 1)     : 0.0f;
        float a110 = p110 ? __ldg(p + HW + W)     : 0.0f;
        float a111 = p111 ? __ldg(p + HW + W + 1) : 0.0f;
        float c000 = p000 ? __ldg(q)              : 0.0f;
        float c001 = p001 ? __ldg(q + 1)          : 0.0f;
        float c010 = p010 ? __ldg(q + W)          : 0.0f;
        float c011 = p011 ? __ldg(q + W + 1)      : 0.0f;
        float c100 = p100 ? __ldg(q + HW)         : 0.0f;
        float c101 = p101 ? __ldg(q + HW + 1)     : 0.0f;
        float c110 = p110 ? __ldg(q + HW + W)     : 0.0f;
        float c111 = p111 ? __ldg(q + HW + W + 1) : 0.0f;

        acc0 = w000 * a000;
        acc0 = fmaf(w001, a001, acc0);
        acc0 = fmaf(w010, a010, acc0);
        acc0 = fmaf(w011, a011, acc0);
        acc0 = fmaf(w100, a100, acc0);
        acc0 = fmaf(w101, a101, acc0);
        acc0 = fmaf(w110, a110, acc0);
        acc0 = fmaf(w111, a111, acc0);

        acc1 = w000 * c000;
        acc1 = fmaf(w001, c001, acc1);
        acc1 = fmaf(w010, c010, acc1);
        acc1 = fmaf(w011, c011, acc1);
        acc1 = fmaf(w100, c100, acc1);
        acc1 = fmaf(w101, c101, acc1);
        acc1 = fmaf(w110, c110, acc1);
        acc1 = fmaf(w111, c111, acc1);
    }

    const size_t ob = (size_t)b * (size_t)(C * DHW) + (size_t)((d * H + h) * W + w);
    out[ob]       = acc0;
    out[ob + DHW] = acc1;
}

extern "C" void kernel_launch(void* const* d_in, const int* in_sizes, int n_in,
                              void* d_out, int out_size)
{
    const float* src = (const float*)d_in[0];
    const float* mat = (const float*)d_in[1];
    float* out = (float*)d_out;

    dim3 block(32, 8, 1);                 // 256 threads = 8 warps; warp = 32 consecutive w
    dim3 grid(W / 32, H / 8, B * D);      // (7, 24, 320) = 53,760 blocks
    affine_grid_sample_kernel<<<grid, block>>>(src, mat, out);
}

// round 8
// speedup vs baseline: 1.0241x; 1.0241x over previous
#include <cuda_runtime.h>
#include <cuda_bf16.h>
#include <cstdint>

constexpr int B = 2, C = 2, D = 160, H = 192, W = 224;
constexpr int HW  = H * W;          // 43008
constexpr int DHW = D * H * W;      // 6,881,280

__global__ __launch_bounds__(224)
void affine_grid_sample_kernel(const float* __restrict__ src,
                               const float* __restrict__ mat,
                               float* __restrict__ out)
{
    const int w  = threadIdx.x;      // 0..W-1
    const int h  = blockIdx.y;       // 0..H-1
    const int zz = blockIdx.z;       // 0..B*D-1
    const int b  = (zz >= D) ? 1 : 0;
    const int d  = zz - (b ? D : 0);

    const float4* m4 = (const float4*)(mat + b * 12);
    const float4 r0 = __ldg(m4 + 0);
    const float4 r1 = __ldg(m4 + 1);
    const float4 r2 = __ldg(m4 + 2);

    const float yn = fmaf((float)h, 2.0f / (H - 1), -1.0f);
    const float zn = fmaf((float)d, 2.0f / (D - 1), -1.0f);
    const float wf = (float)w;

    const float hw_ = 0.5f * (W - 1);
    const float hh_ = 0.5f * (H - 1);
    const float hd_ = 0.5f * (D - 1);

    // ix = r0.x*w + hw_*(r0.y*yn + r0.z*zn + r0.w/D + 1 - r0.x), etc.
    const float tx = fmaf(r0.y, yn, fmaf(r0.z, zn, fmaf(r0.w, 1.0f / D, 1.0f - r0.x)));
    const float ty = fmaf(r1.y, yn, fmaf(r1.z, zn, fmaf(r1.w, 1.0f / H, 1.0f - r1.x)));
    const float tz = fmaf(r2.y, yn, fmaf(r2.z, zn, fmaf(r2.w, 1.0f / W, 1.0f - r2.x)));

    const float ix = fmaf(r0.x,               wf, tx * hw_);
    const float iy = fmaf(r1.x * (hh_ / hw_), wf, ty * hh_);
    const float iz = fmaf(r2.x * (hd_ / hw_), wf, tz * hd_);

    const float fx0 = floorf(ix), fy0 = floorf(iy), fz0 = floorf(iz);
    const float fx = ix - fx0, fy = iy - fy0, fz = iz - fz0;
    const int x0 = (int)fx0, y0 = (int)fy0, z0 = (int)fz0;

    // per-corner validity (branch-free, round-2 style: fastest measured)
    const bool vx0 = (unsigned)x0       < (unsigned)W;
    const bool vx1 = (unsigned)(x0 + 1) < (unsigned)W;
    const bool vy0 = (unsigned)y0       < (unsigned)H;
    const bool vy1 = (unsigned)(y0 + 1) < (unsigned)H;
    const bool vz0 = (unsigned)z0       < (unsigned)D;
    const bool vz1 = (unsigned)(z0 + 1) < (unsigned)D;

    const bool p000 = vz0 & vy0 & vx0, p001 = vz0 & vy0 & vx1;
    const bool p010 = vz0 & vy1 & vx0, p011 = vz0 & vy1 & vx1;
    const bool p100 = vz1 & vy0 & vx0, p101 = vz1 & vy0 & vx1;
    const bool p110 = vz1 & vy1 & vx0, p111 = vz1 & vy1 & vx1;

    // trilinear weights
    const float wx1 = fx, wx0 = 1.0f - fx;
    const float wy1 = fy, wy0 = 1.0f - fy;
    const float wz1 = fz, wz0 = 1.0f - fz;
    const float w00 = wz0 * wy0, w01 = wz0 * wy1;
    const float w10 = wz1 * wy0, w11 = wz1 * wy1;
    const float w000 = w00 * wx0, w001 = w00 * wx1;
    const float w010 = w01 * wx0, w011 = w01 * wx1;
    const float w100 = w10 * wx0, w101 = w10 * wx1;
    const float w110 = w11 * wx0, w111 = w11 * wx1;

    const float* sb = src + (size_t)b * (size_t)(C * DHW);
    const float* p  = sb + ((size_t)((z0 * H + y0) * W + x0));
    const float* q  = p + DHW;

    // ---- channel 0: batch of 8 LDG (MLP_p1 = 8) ----
    float a000 = p000 ? __ldg(p)              : 0.0f;
    float a001 = p001 ? __ldg(p + 1)          : 0.0f;
    float a010 = p010 ? __ldg(p + W)          : 0.0f;
    float a011 = p011 ? __ldg(p + W + 1)      : 0.0f;
    float a100 = p100 ? __ldg(p + HW)         : 0.0f;
    float a101 = p101 ? __ldg(p + HW + 1)     : 0.0f;
    float a110 = p110 ? __ldg(p + HW + W)     : 0.0f;
    float a111 = p111 ? __ldg(p + HW + W + 1) : 0.0f;

    float acc0 = w000 * a000;
    acc0 = fmaf(w001, a001, acc0);
    acc0 = fmaf(w010, a010, acc0);
    acc0 = fmaf(w011, a011, acc0);
    acc0 = fmaf(w100, a100, acc0);
    acc0 = fmaf(w101, a101, acc0);
    acc0 = fmaf(w110, a110, acc0);
    acc0 = fmaf(w111, a111, acc0);

    // scheduling fence: keep channel-1 LDGs from being hoisted into the
    // channel-0 batch (caps front-batched MLP_p1 at 8, halving the
    // cross-CTA L1tex queue depth at occupancy 8). Emits no instructions.
    asm volatile("" ::: "memory");

    // ---- channel 1: second batch of 8 LDG ----
    float c000 = p000 ? __ldg(q)              : 0.0f;
    float c001 = p001 ? __ldg(q + 1)          : 0.0f;
    float c010 = p010 ? __ldg(q + W)          : 0.0f;
    float c011 = p011 ? __ldg(q + W + 1)      : 0.0f;
    float c100 = p100 ? __ldg(q + HW)         : 0.0f;
    float c101 = p101 ? __ldg(q + HW + 1)     : 0.0f;
    float c110 = p110 ? __ldg(q + HW + W)     : 0.0f;
    float c111 = p111 ? __ldg(q + HW + W + 1) : 0.0f;

    float acc1 = w000 * c000;
    acc1 = fmaf(w001, c001, acc1);
    acc1 = fmaf(w010, c010, acc1);
    acc1 = fmaf(w011, c011, acc1);
    acc1 = fmaf(w100, c100, acc1);
    acc1 = fmaf(w101, c101, acc1);
    acc1 = fmaf(w110, c110, acc1);
    acc1 = fmaf(w111, c111, acc1);

    const size_t ob = (size_t)b * (size_t)(C * DHW) + (size_t)((d * H + h) * W + w);
    out[ob]       = acc0;
    out[ob + DHW] = acc1;
}

extern "C" void kernel_launch(void* const* d_in, const int* in_sizes, int n_in,
                              void* d_out, int out_size)
{
    const float* src = (const float*)d_in[0];
    const float* mat = (const float*)d_in[1];
    float* out = (float*)d_out;

    dim3 block(W, 1, 1);          // 224 threads = 7 warps (round-2 config)
    dim3 grid(1, H, B * D);       // (1, 192, 320)
    affine_grid_sample_kernel<<<grid, block>>>(src, mat, out);
}